// round 3
// baseline (speedup 1.0000x reference)
#include <cuda_runtime.h>

// CrossCompressUnit: rank-1 cross compress.
// v_out = v * (e.w_vv) + e * (v.w_ev) + b_v
// e_out = v * (e.w_ve) + e * (v.w_ee) + b_e
//
// One warp per row, 2 rows per loop iteration (4 LDG.128 in flight).
// 8 independent shuffle-butterfly reductions interleaved so the 5 dependent
// stages pipeline across chains. (redux.sync.f32 does NOT exist on sm_103.)

#define D 128

__device__ __forceinline__ float dot4(float4 a, float4 b) {
    return fmaf(a.x, b.x, fmaf(a.y, b.y, fmaf(a.z, b.z, a.w * b.w)));
}

__global__ __launch_bounds__(256)
void cross_compress_kernel(const float* __restrict__ v,
                           const float* __restrict__ e,
                           const float* __restrict__ w_vv,
                           const float* __restrict__ w_ev,
                           const float* __restrict__ w_ve,
                           const float* __restrict__ w_ee,
                           const float* __restrict__ b_v,
                           const float* __restrict__ b_e,
                           float* __restrict__ out,   // [2*B*D]: v_out then e_out
                           int B)
{
    const int lane            = threadIdx.x & 31;
    const int warp_in_block   = threadIdx.x >> 5;
    const int warps_per_block = blockDim.x >> 5;
    const int gwarp  = blockIdx.x * warps_per_block + warp_in_block;
    const int nwarps = gridDim.x * warps_per_block;

    const int c = lane * 4;   // column base for this lane

    // Per-lane weight slices, register-resident across the row loop (3KB, L2-hot).
    const float4 wvv = *reinterpret_cast<const float4*>(w_vv + c);
    const float4 wev = *reinterpret_cast<const float4*>(w_ev + c);
    const float4 wve = *reinterpret_cast<const float4*>(w_ve + c);
    const float4 wee = *reinterpret_cast<const float4*>(w_ee + c);
    const float4 bv  = *reinterpret_cast<const float4*>(b_v  + c);
    const float4 be  = *reinterpret_cast<const float4*>(b_e  + c);

    float* out_v = out;
    float* out_e = out + (size_t)B * D;

    for (int row = gwarp * 2; row < B; row += nwarps * 2) {
        const int  rowb    = row + 1;
        const bool have_b  = rowb < B;
        const size_t basea = (size_t)row  * D + c;
        const size_t baseb = (size_t)rowb * D + c;

        // Issue all loads first: 4 independent LDG.128 in flight (streaming).
        const float4 va = __ldcs(reinterpret_cast<const float4*>(v + basea));
        const float4 ea = __ldcs(reinterpret_cast<const float4*>(e + basea));
        float4 vb, eb;
        if (have_b) {
            vb = __ldcs(reinterpret_cast<const float4*>(v + baseb));
            eb = __ldcs(reinterpret_cast<const float4*>(e + baseb));
        } else {
            vb = make_float4(0.f, 0.f, 0.f, 0.f);
            eb = vb;
        }

        // Per-lane partial dots for both rows: 8 independent values.
        float a_vv = dot4(ea, wvv);
        float a_ev = dot4(va, wev);
        float a_ve = dot4(ea, wve);
        float a_ee = dot4(va, wee);
        float c_vv = dot4(eb, wvv);
        float c_ev = dot4(vb, wev);
        float c_ve = dot4(eb, wve);
        float c_ee = dot4(vb, wee);

        // 8 interleaved butterfly reductions — chains pipeline per stage.
        #pragma unroll
        for (int off = 16; off > 0; off >>= 1) {
            a_vv += __shfl_xor_sync(0xffffffffu, a_vv, off);
            a_ev += __shfl_xor_sync(0xffffffffu, a_ev, off);
            a_ve += __shfl_xor_sync(0xffffffffu, a_ve, off);
            a_ee += __shfl_xor_sync(0xffffffffu, a_ee, off);
            c_vv += __shfl_xor_sync(0xffffffffu, c_vv, off);
            c_ev += __shfl_xor_sync(0xffffffffu, c_ev, off);
            c_ve += __shfl_xor_sync(0xffffffffu, c_ve, off);
            c_ee += __shfl_xor_sync(0xffffffffu, c_ee, off);
        }

        float4 vo, eo;
        vo.x = fmaf(va.x, a_vv, fmaf(ea.x, a_ev, bv.x));
        vo.y = fmaf(va.y, a_vv, fmaf(ea.y, a_ev, bv.y));
        vo.z = fmaf(va.z, a_vv, fmaf(ea.z, a_ev, bv.z));
        vo.w = fmaf(va.w, a_vv, fmaf(ea.w, a_ev, bv.w));
        eo.x = fmaf(va.x, a_ve, fmaf(ea.x, a_ee, be.x));
        eo.y = fmaf(va.y, a_ve, fmaf(ea.y, a_ee, be.y));
        eo.z = fmaf(va.z, a_ve, fmaf(ea.z, a_ee, be.z));
        eo.w = fmaf(va.w, a_ve, fmaf(ea.w, a_ee, be.w));
        __stcs(reinterpret_cast<float4*>(out_v + basea), vo);
        __stcs(reinterpret_cast<float4*>(out_e + basea), eo);

        if (have_b) {
            float4 vo2, eo2;
            vo2.x = fmaf(vb.x, c_vv, fmaf(eb.x, c_ev, bv.x));
            vo2.y = fmaf(vb.y, c_vv, fmaf(eb.y, c_ev, bv.y));
            vo2.z = fmaf(vb.z, c_vv, fmaf(eb.z, c_ev, bv.z));
            vo2.w = fmaf(vb.w, c_vv, fmaf(eb.w, c_ev, bv.w));
            eo2.x = fmaf(vb.x, c_ve, fmaf(eb.x, c_ee, be.x));
            eo2.y = fmaf(vb.y, c_ve, fmaf(eb.y, c_ee, be.y));
            eo2.z = fmaf(vb.z, c_ve, fmaf(eb.z, c_ee, be.z));
            eo2.w = fmaf(vb.w, c_ve, fmaf(eb.w, c_ee, be.w));
            __stcs(reinterpret_cast<float4*>(out_v + baseb), vo2);
            __stcs(reinterpret_cast<float4*>(out_e + baseb), eo2);
        }
    }
}

extern "C" void kernel_launch(void* const* d_in, const int* in_sizes, int n_in,
                              void* d_out, int out_size)
{
    const float* v    = (const float*)d_in[0];
    const float* e    = (const float*)d_in[1];
    const float* w_vv = (const float*)d_in[2];
    const float* w_ev = (const float*)d_in[3];
    const float* w_ve = (const float*)d_in[4];
    const float* w_ee = (const float*)d_in[5];
    const float* b_v  = (const float*)d_in[6];
    const float* b_e  = (const float*)d_in[7];
    float* out = (float*)d_out;

    const int B = in_sizes[0] / D;   // rows

    const int threads = 256;
    const int warps_per_block = threads / 32;   // 8
    // 4 rows per warp (2 iterations of 2) -> more CTAs for latency hiding.
    int blocks = (B + warps_per_block * 4 - 1) / (warps_per_block * 4);
    if (blocks < 1) blocks = 1;

    cross_compress_kernel<<<blocks, threads>>>(v, e, w_vv, w_ev, w_ve, w_ee,
                                               b_v, b_e, out, B);
}

// round 4
// speedup vs baseline: 1.0808x; 1.0808x over previous
#include <cuda_runtime.h>

// CrossCompressUnit: rank-1 cross compress.
// v_out = v * (e.w_vv) + e * (v.w_ev) + b_v
// e_out = v * (e.w_ve) + e * (v.w_ee) + b_e
//
// One warp per row. Packed 4-way warp reduction (10 SHFLs instead of 20):
//   xor16 merges (p0,p2) -> u and (p1,p3) -> w  (2 SHFL)
//   xor8 repartitions so 8-lane group g owns dot g (1 SHFL)
//   3-stage butterfly within groups (3 SHFL)
//   4 broadcasts (4 SHFL)
// Next row's loads are prefetched before the current row's reduction so
// DRAM requests stay in flight behind the shuffle chain.

#define D 128

__device__ __forceinline__ float dot4(float4 a, float4 b) {
    return fmaf(a.x, b.x, fmaf(a.y, b.y, fmaf(a.z, b.z, a.w * b.w)));
}

__global__ __launch_bounds__(256)
void cross_compress_kernel(const float* __restrict__ v,
                           const float* __restrict__ e,
                           const float* __restrict__ w_vv,
                           const float* __restrict__ w_ev,
                           const float* __restrict__ w_ve,
                           const float* __restrict__ w_ee,
                           const float* __restrict__ b_v,
                           const float* __restrict__ b_e,
                           float* __restrict__ out,   // [2*B*D]: v_out then e_out
                           int B)
{
    const unsigned FULL = 0xffffffffu;
    const int lane            = threadIdx.x & 31;
    const int warp_in_block   = threadIdx.x >> 5;
    const int warps_per_block = blockDim.x >> 5;
    const int gwarp  = blockIdx.x * warps_per_block + warp_in_block;
    const int nwarps = gridDim.x * warps_per_block;

    const int c = lane * 4;   // column base for this lane

    // Per-lane weight slices, register-resident (3KB total, L2-hot).
    const float4 wvv = *reinterpret_cast<const float4*>(w_vv + c);
    const float4 wev = *reinterpret_cast<const float4*>(w_ev + c);
    const float4 wve = *reinterpret_cast<const float4*>(w_ve + c);
    const float4 wee = *reinterpret_cast<const float4*>(w_ee + c);
    const float4 bv  = *reinterpret_cast<const float4*>(b_v  + c);
    const float4 be  = *reinterpret_cast<const float4*>(b_e  + c);

    float* out_v = out;
    float* out_e = out + (size_t)B * D;

    const bool hi16 = (lane & 16) != 0;
    const bool hi8  = (lane & 8)  != 0;

    int row = gwarp;
    float4 v_cur = make_float4(0.f, 0.f, 0.f, 0.f);
    float4 e_cur = v_cur;
    if (row < B) {
        const size_t base = (size_t)row * D + c;
        v_cur = __ldcs(reinterpret_cast<const float4*>(v + base));
        e_cur = __ldcs(reinterpret_cast<const float4*>(e + base));
    }

    for (; row < B; row += nwarps) {
        // Prefetch next row: 2 LDG.128 in flight during the reduction below.
        const int nrow = row + nwarps;
        float4 v_nxt = make_float4(0.f, 0.f, 0.f, 0.f);
        float4 e_nxt = v_nxt;
        if (nrow < B) {
            const size_t nbase = (size_t)nrow * D + c;
            v_nxt = __ldcs(reinterpret_cast<const float4*>(v + nbase));
            e_nxt = __ldcs(reinterpret_cast<const float4*>(e + nbase));
        }

        // Per-lane partials.
        float p0 = dot4(e_cur, wvv);   // e . w_vv
        float p1 = dot4(v_cur, wev);   // v . w_ev
        float p2 = dot4(e_cur, wve);   // e . w_ve
        float p3 = dot4(v_cur, wee);   // v . w_ee

        // Stage 1 (xor16): lanes<16 accumulate p0/p1, lanes>=16 accumulate p2/p3.
        float r1 = __shfl_xor_sync(FULL, hi16 ? p0 : p2, 16);
        float u  = (hi16 ? p2 : p0) + r1;
        float r2 = __shfl_xor_sync(FULL, hi16 ? p1 : p3, 16);
        float w  = (hi16 ? p3 : p1) + r2;

        // Stage 2 (xor8): 8-lane group g ends up owning dot g.
        float r3 = __shfl_xor_sync(FULL, hi8 ? u : w, 8);
        float s  = (hi8 ? w : u) + r3;

        // Stages 3-5: butterfly within 8-lane groups.
        s += __shfl_xor_sync(FULL, s, 4);
        s += __shfl_xor_sync(FULL, s, 2);
        s += __shfl_xor_sync(FULL, s, 1);

        // Broadcast the four dots to all lanes.
        const float d_vv = __shfl_sync(FULL, s, 0);
        const float d_ev = __shfl_sync(FULL, s, 8);
        const float d_ve = __shfl_sync(FULL, s, 16);
        const float d_ee = __shfl_sync(FULL, s, 24);

        float4 vo, eo;
        vo.x = fmaf(v_cur.x, d_vv, fmaf(e_cur.x, d_ev, bv.x));
        vo.y = fmaf(v_cur.y, d_vv, fmaf(e_cur.y, d_ev, bv.y));
        vo.z = fmaf(v_cur.z, d_vv, fmaf(e_cur.z, d_ev, bv.z));
        vo.w = fmaf(v_cur.w, d_vv, fmaf(e_cur.w, d_ev, bv.w));
        eo.x = fmaf(v_cur.x, d_ve, fmaf(e_cur.x, d_ee, be.x));
        eo.y = fmaf(v_cur.y, d_ve, fmaf(e_cur.y, d_ee, be.y));
        eo.z = fmaf(v_cur.z, d_ve, fmaf(e_cur.z, d_ee, be.z));
        eo.w = fmaf(v_cur.w, d_ve, fmaf(e_cur.w, d_ee, be.w));

        const size_t base = (size_t)row * D + c;
        __stcs(reinterpret_cast<float4*>(out_v + base), vo);
        __stcs(reinterpret_cast<float4*>(out_e + base), eo);

        v_cur = v_nxt;
        e_cur = e_nxt;
    }
}

extern "C" void kernel_launch(void* const* d_in, const int* in_sizes, int n_in,
                              void* d_out, int out_size)
{
    const float* v    = (const float*)d_in[0];
    const float* e    = (const float*)d_in[1];
    const float* w_vv = (const float*)d_in[2];
    const float* w_ev = (const float*)d_in[3];
    const float* w_ve = (const float*)d_in[4];
    const float* w_ee = (const float*)d_in[5];
    const float* b_v  = (const float*)d_in[6];
    const float* b_e  = (const float*)d_in[7];
    float* out = (float*)d_out;

    const int B = in_sizes[0] / D;   // rows

    const int threads = 256;
    const int warps_per_block = threads / 32;   // 8
    // 8 rows per warp -> enough loop trips for prefetch pipelining.
    int blocks = (B + warps_per_block * 8 - 1) / (warps_per_block * 8);
    if (blocks < 1) blocks = 1;

    cross_compress_kernel<<<blocks, threads>>>(v, e, w_vv, w_ev, w_ve, w_ee,
                                               b_v, b_e, out, B);
}